// round 1
// baseline (speedup 1.0000x reference)
#include <cuda_runtime.h>
#include <cuda_bf16.h>
#include <math.h>

// Problem dims (fixed by the dataset)
#define B 32
#define S 2048
#define D 1024
#define K 10
#define NCHUNK 16              // s-chunks for partial mean
#define SCHUNK (S / NCHUNK)    // 128 rows per chunk
#define D4 (D / 4)             // 256 float4 per row

#define ALPHA_BASE 0.3f
#define MAX_DELTA 0.5f
#define EPS_WHITEN 1e-8f
#define EPS_NORM 1e-8f
#define EPS_FNORM 1e-12f

// Scratch (device globals -> no allocation)
__device__ float g_partial[B * NCHUNK * D];  // 2 MB
__device__ float g_vraw[B * D];              // 128 KB
__device__ float g_corr[B * D];              // 128 KB

// ---------------------------------------------------------------------------
// Kernel 1: partial sums over sequence chunks. grid = (NCHUNK, B), 256 thr.
// Each thread owns one float4 column slice, sums 128 rows.
// ---------------------------------------------------------------------------
__global__ void k_partial(const float* __restrict__ h) {
    int chunk = blockIdx.x;
    int b = blockIdx.y;
    int t = threadIdx.x;  // 0..255 -> float4 index in D
    const float4* hp = reinterpret_cast<const float4*>(h)
                       + (size_t)(b * S + chunk * SCHUNK) * D4 + t;
    float ax = 0.f, ay = 0.f, az = 0.f, aw = 0.f;
#pragma unroll 8
    for (int s = 0; s < SCHUNK; s++) {
        float4 v = __ldg(hp + (size_t)s * D4);
        ax += v.x; ay += v.y; az += v.z; aw += v.w;
    }
    float4 out = make_float4(ax, ay, az, aw);
    reinterpret_cast<float4*>(g_partial)[(b * NCHUNK + chunk) * D4 + t] = out;
}

// ---------------------------------------------------------------------------
// Kernel 2: reduce chunks -> v_raw (mean over S). grid = B, 256 thr.
// ---------------------------------------------------------------------------
__global__ void k_finalize(void) {
    int b = blockIdx.x;
    int t = threadIdx.x;
    float ax = 0.f, ay = 0.f, az = 0.f, aw = 0.f;
#pragma unroll
    for (int c = 0; c < NCHUNK; c++) {
        float4 v = reinterpret_cast<const float4*>(g_partial)[(b * NCHUNK + c) * D4 + t];
        ax += v.x; ay += v.y; az += v.z; aw += v.w;
    }
    const float inv = 1.0f / (float)S;
    reinterpret_cast<float4*>(g_vraw)[b * D4 + t] =
        make_float4(ax * inv, ay * inv, az * inv, aw * inv);
}

// ---------------------------------------------------------------------------
// Kernel 3: per-batch snap. grid = B, 256 threads (each thread owns 4 d's).
// Each block redundantly computes whitening stats + attractor norms (cheap,
// all from L2), then cos[b][k], argmax, and correction[b][:].
// ---------------------------------------------------------------------------
__device__ __forceinline__ float warp_sum(float x) {
#pragma unroll
    for (int o = 16; o > 0; o >>= 1) x += __shfl_down_sync(0xffffffffu, x, o);
    return x;
}

// Reduce 10 per-thread values across a 256-thread block into out[0..9].
__device__ __forceinline__ void block_reduce10(const float* v, float (*red)[8],
                                               float* out, int lane, int wid,
                                               int t) {
#pragma unroll
    for (int k = 0; k < K; k++) {
        float x = warp_sum(v[k]);
        if (lane == 0) red[k][wid] = x;
    }
    __syncthreads();
    if (t < K) {
        float s = 0.f;
#pragma unroll
        for (int j = 0; j < 8; j++) s += red[t][j];
        out[t] = s;
    }
    __syncthreads();
}

__global__ void k_snap(const float* __restrict__ attractors) {
    __shared__ float red[K][8];
    __shared__ float ss1S[K];   // sum of squares of raw attractors
    __shared__ float ss2S[K];   // sum of squares after first normalize
    __shared__ float cosS[K];
    __shared__ float inv1S[K];  // 1 / max(norm1, EPS_NORM)
    __shared__ float bestScoreS;
    __shared__ int bestIdxS;

    int b = blockIdx.x;
    int t = threadIdx.x;
    int lane = t & 31, wid = t >> 5;

    const float4* vr4 = reinterpret_cast<const float4*>(g_vraw);

    // ---- whitening stats over the batch for this thread's 4 d's ----
    float4 sum = make_float4(0, 0, 0, 0), ssq = make_float4(0, 0, 0, 0);
    float4 vrb = make_float4(0, 0, 0, 0);
#pragma unroll 4
    for (int bb = 0; bb < B; bb++) {
        float4 v = __ldg(vr4 + bb * D4 + t);
        sum.x += v.x; sum.y += v.y; sum.z += v.z; sum.w += v.w;
        ssq.x += v.x * v.x; ssq.y += v.y * v.y;
        ssq.z += v.z * v.z; ssq.w += v.w * v.w;
        if (bb == b) vrb = v;
    }
    const float invB = 1.0f / (float)B;
    float4 mean = make_float4(sum.x * invB, sum.y * invB, sum.z * invB, sum.w * invB);
    float4 var = make_float4(ssq.x * invB - mean.x * mean.x,
                             ssq.y * invB - mean.y * mean.y,
                             ssq.z * invB - mean.z * mean.z,
                             ssq.w * invB - mean.w * mean.w);
    float4 rstd = make_float4(rsqrtf(var.x + EPS_WHITEN), rsqrtf(var.y + EPS_WHITEN),
                              rsqrtf(var.z + EPS_WHITEN), rsqrtf(var.w + EPS_WHITEN));
    float4 vn = make_float4((vrb.x - mean.x) * rstd.x, (vrb.y - mean.y) * rstd.y,
                            (vrb.z - mean.z) * rstd.z, (vrb.w - mean.w) * rstd.w);

    // ---- attractor normalization ----
    const float4* a4p = reinterpret_cast<const float4*>(attractors);
    float4 a[K];
    float acc[K];
#pragma unroll
    for (int k = 0; k < K; k++) {
        a[k] = __ldg(a4p + k * D4 + t);
        acc[k] = a[k].x * a[k].x + a[k].y * a[k].y + a[k].z * a[k].z + a[k].w * a[k].w;
    }
    block_reduce10(acc, red, ss1S, lane, wid, t);
    if (t < K) inv1S[t] = 1.0f / fmaxf(sqrtf(ss1S[t]), EPS_NORM);
    __syncthreads();

    // att = raw * inv1 (this is 'att' used for 'closest'); apply to regs
#pragma unroll
    for (int k = 0; k < K; k++) {
        float s1 = inv1S[k];
        a[k].x *= s1; a[k].y *= s1; a[k].z *= s1; a[k].w *= s1;
        acc[k] = a[k].x * a[k].x + a[k].y * a[k].y + a[k].z * a[k].z + a[k].w * a[k].w;
    }
    block_reduce10(acc, red, ss2S, lane, wid, t);

    // att_norm = att / max(||att||, EPS_FNORM); then cos contributions
#pragma unroll
    for (int k = 0; k < K; k++) {
        float s2 = 1.0f / fmaxf(sqrtf(ss2S[k]), EPS_FNORM);
        float anx = a[k].x * s2, any = a[k].y * s2, anz = a[k].z * s2, anw = a[k].w * s2;
        acc[k] = vn.x * anx + vn.y * any + vn.z * anz + vn.w * anw;
    }
    block_reduce10(acc, red, cosS, lane, wid, t);

    if (t == 0) {
        float best = cosS[0];
        int bi = 0;
#pragma unroll
        for (int k = 1; k < K; k++) {
            if (cosS[k] > best) { best = cosS[k]; bi = k; }  // strict > keeps first max
        }
        bestScoreS = best;
        bestIdxS = bi;
    }
    __syncthreads();

    // ---- snap + correction ----
    float alpha = ALPHA_BASE * (1.0f - bestScoreS);
    int bi = bestIdxS;
    float s1 = inv1S[bi];
    float4 craw = __ldg(a4p + bi * D4 + t);
    float cx = craw.x * s1, cy = craw.y * s1, cz = craw.z * s1, cw = craw.w * s1;

    float dx = fminf(fmaxf(cx - vn.x, -MAX_DELTA), MAX_DELTA);
    float dy = fminf(fmaxf(cy - vn.y, -MAX_DELTA), MAX_DELTA);
    float dz = fminf(fmaxf(cz - vn.z, -MAX_DELTA), MAX_DELTA);
    float dw = fminf(fmaxf(cw - vn.w, -MAX_DELTA), MAX_DELTA);

    float4 corr = make_float4(vn.x + alpha * dx - vrb.x,
                              vn.y + alpha * dy - vrb.y,
                              vn.z + alpha * dz - vrb.z,
                              vn.w + alpha * dw - vrb.w);
    reinterpret_cast<float4*>(g_corr)[b * D4 + t] = corr;
}

// ---------------------------------------------------------------------------
// Kernel 4: out = hidden + correction[b][d]   (the big 512 MB pass)
// ---------------------------------------------------------------------------
__global__ void k_add(const float* __restrict__ h, float* __restrict__ out) {
    const float4* h4 = reinterpret_cast<const float4*>(h);
    float4* o4 = reinterpret_cast<float4*>(out);
    const float4* c4 = reinterpret_cast<const float4*>(g_corr);
    const int total = B * S * D4;  // 16,777,216 float4
    const int perB = S * D4;       // 524288 = 2^19
    for (int i = blockIdx.x * blockDim.x + threadIdx.x; i < total;
         i += gridDim.x * blockDim.x) {
        int b = i >> 19;
        int c = i & (D4 - 1);
        float4 hv = h4[i];
        float4 cv = __ldg(c4 + (b << 8) + c);
        o4[i] = make_float4(hv.x + cv.x, hv.y + cv.y, hv.z + cv.z, hv.w + cv.w);
        (void)perB;
    }
}

// ---------------------------------------------------------------------------
extern "C" void kernel_launch(void* const* d_in, const int* in_sizes, int n_in,
                              void* d_out, int out_size) {
    const float* hidden = (const float*)d_in[0];      // [B, S, D]
    const float* attractors = (const float*)d_in[1];  // [K, D]
    float* out = (float*)d_out;
    (void)in_sizes; (void)n_in; (void)out_size;

    dim3 g1(NCHUNK, B);
    k_partial<<<g1, 256>>>(hidden);
    k_finalize<<<B, 256>>>();
    k_snap<<<B, 256>>>(attractors);
    k_add<<<2048, 256>>>(hidden, out);
}